// round 1
// baseline (speedup 1.0000x reference)
#include <cuda_runtime.h>
#include <math_constants.h>

// Imputer: x[B,D,N,S], B=64, D=2, N=2048, S=128 fp32.
// For each (b,n): d* = first d whose row has any -inf; mean = mean of valid
// entries of row (b,d*,n,:); every -inf at (b,*,n,*) is replaced by mean.
// One warp per (b,n): 2 float4 loads + 2 float4 stores per lane.

#define B_ 64
#define D_ 2
#define N_ 2048
#define S_ 128

__global__ void __launch_bounds__(256) imputer_kernel(
    const float4* __restrict__ x, float4* __restrict__ out)
{
    const unsigned gtid   = blockIdx.x * blockDim.x + threadIdx.x;
    const unsigned warp   = gtid >> 5;          // one warp per (b,n)
    const unsigned lane   = gtid & 31u;
    if (warp >= B_ * N_) return;

    const unsigned b = warp >> 11;              // / N_
    const unsigned n = warp & (N_ - 1);

    // float4-unit offsets
    const unsigned row_f4   = S_ / 4;                   // 32
    const unsigned dstride  = (N_ * S_) / 4;            // 65536
    const unsigned base0    = b * (D_ * dstride) + n * row_f4 + lane;
    const unsigned base1    = base0 + dstride;

    float4 v0 = x[base0];
    float4 v1 = x[base1];

    const float NEG_INF = -CUDART_INF_F;

    // per-lane stats for each row
    float s0 = 0.f, s1 = 0.f;
    int   c0 = 0,   c1 = 0;
    bool  m0 = false, m1 = false;

    #define ACC(v, comp, S, C, M)                    \
        do { float t = (v).comp;                     \
             if (t == NEG_INF) { M = true; }         \
             else { S += t; C += 1; } } while (0)

    ACC(v0, x, s0, c0, m0); ACC(v0, y, s0, c0, m0);
    ACC(v0, z, s0, c0, m0); ACC(v0, w, s0, c0, m0);
    ACC(v1, x, s1, c1, m1); ACC(v1, y, s1, c1, m1);
    ACC(v1, z, s1, c1, m1); ACC(v1, w, s1, c1, m1);
    #undef ACC

    // d* = 0 if row 0 has any missing, else 1 (argmax of [has0, has1]).
    const unsigned miss0 = __ballot_sync(0xffffffffu, m0);
    const bool use0 = (miss0 != 0u);

    float s = use0 ? s0 : s1;
    float c = use0 ? (float)c0 : (float)c1;

    #pragma unroll
    for (int o = 16; o > 0; o >>= 1) {
        s += __shfl_xor_sync(0xffffffffu, s, o);
        c += __shfl_xor_sync(0xffffffffu, c, o);
    }
    const float mean = s / fmaxf(c, 1.0f);

    // fill and store
    float4 o0, o1;
    o0.x = (v0.x == NEG_INF) ? mean : v0.x;
    o0.y = (v0.y == NEG_INF) ? mean : v0.y;
    o0.z = (v0.z == NEG_INF) ? mean : v0.z;
    o0.w = (v0.w == NEG_INF) ? mean : v0.w;
    o1.x = (v1.x == NEG_INF) ? mean : v1.x;
    o1.y = (v1.y == NEG_INF) ? mean : v1.y;
    o1.z = (v1.z == NEG_INF) ? mean : v1.z;
    o1.w = (v1.w == NEG_INF) ? mean : v1.w;

    out[base0] = o0;
    out[base1] = o1;
}

extern "C" void kernel_launch(void* const* d_in, const int* in_sizes, int n_in,
                              void* d_out, int out_size)
{
    (void)in_sizes; (void)n_in; (void)out_size;
    const float4* x   = (const float4*)d_in[0];
    float4*       out = (float4*)d_out;

    const int total_warps   = B_ * N_;            // 131072
    const int threads       = 256;                // 8 warps/block
    const int blocks        = (total_warps * 32) / threads;  // 16384

    imputer_kernel<<<blocks, threads>>>(x, out);
}